// round 4
// baseline (speedup 1.0000x reference)
#include <cuda_runtime.h>
#include <math.h>

// Problem constants (fixed by setup_inputs)
#define WSZ   8
#define NHEAD 6
#define HDIM  32
#define CDIM  192
#define BIMG  4
#define HH    256
#define WW    256
#define NPIX  (BIMG*HH*WW)        // 262144
#define NWIN  (BIMG*(HH/WSZ)*(WW/WSZ)) // 4096

// ---------------- scratch (device globals; no allocation allowed) ----------
__device__ __align__(16) float g_v  [NPIX*192];
__device__ __align__(16) float g_qk1[NPIX*128];
__device__ __align__(16) float g_t3a[NPIX*32];
__device__ __align__(16) float g_t3b[NPIX*32];
__device__ __align__(16) float g_qk3[NPIX*128];
__device__ __align__(16) float g_t5a[NPIX*16];
__device__ __align__(16) float g_t5b[NPIX*16];
__device__ __align__(16) float g_qk5[NPIX*128];
__device__ __align__(16) float g_pre[NPIX*192];
// repacked conv weights: (OC, K) with k = (kh*KW+kw)*IC + ic
__device__ __align__(16) float g_w3a[32*192*9];
__device__ __align__(16) float g_w3c[128*32*9];
__device__ __align__(16) float g_w5a[16*192*25];
__device__ __align__(16) float g_w5c[128*16*25];

// ---------------- weight repack: (OC,IC,KH,KW) -> (OC, tap*IC+ic) ---------
__global__ void repack_w(const float* __restrict__ src, float* __restrict__ dst,
                         int OC, int IC, int KH, int KW) {
    int Kt = IC * KH * KW;
    int i = blockIdx.x * 256 + threadIdx.x;
    if (i >= OC * Kt) return;
    int oc = i / Kt, k = i % Kt;
    int ic = k % IC;
    int tap = k / IC;
    int kh = tap / KW, kw = tap % KW;
    dst[i] = src[((size_t)(oc * IC + ic) * KH + kh) * KW + kw];
}

// ---------------- implicit-GEMM conv (NHWC in, NHWC out) -------------------
// out[p, oc] = act( bias[oc] + sum_k A[p,k] * W[oc,k] ),  k = tap*IC + ic
// A[p,k] gathered on the fly with spatial shift + zero padding.
// Tile: 64 pixels x 64 oc x 16 k.  256 threads, 4x4 micro-tile per thread.
__global__ void __launch_bounds__(256)
conv_gemm(const float* __restrict__ in, const float* __restrict__ wt,
          const float* __restrict__ bias, float* __restrict__ out,
          int Hh, int Wd, int IC, int OC, int KH, int KW, int pad, int act) {
    const int Ktot = IC * KH * KW;
    __shared__ float As[16][64];
    __shared__ float Wsm[16][64];

    const int tid = threadIdx.x;
    const int pb = blockIdx.x * 64;
    const int ob = blockIdx.y * 64;

    // A-loader mapping: thread -> (pixel, 4 consecutive k)
    const int apix = tid >> 2;
    const int akg  = (tid & 3) * 4;
    const int pidx = pb + apix;
    const int bimg = pidx / (Hh * Wd);
    const int ry   = (pidx / Wd) % Hh;
    const int rx   = pidx % Wd;

    // W-loader mapping
    const int woc = tid >> 2;
    const int wkg = (tid & 3) * 4;
    const bool wvalid = (ob + woc) < OC;
    const float* wrow = wt + (size_t)(ob + woc) * Ktot;

    const int ty = tid >> 4;   // 0..15 -> pixel group
    const int tx = tid & 15;   // 0..15 -> oc group

    float acc[4][4];
#pragma unroll
    for (int i = 0; i < 4; i++)
#pragma unroll
        for (int j = 0; j < 4; j++) acc[i][j] = 0.f;

    for (int k0 = 0; k0 < Ktot; k0 += 16) {
        // ---- load A tile (im2col on the fly) ----
        {
            int kk  = k0 + akg;
            int ic  = kk % IC;           // 4 consecutive k share one tap (IC%4==0)
            int tap = kk / IC;
            int kh  = tap / KW, kw = tap % KW;
            int yy  = ry + kh - pad, xx = rx + kw - pad;
            float4 av = make_float4(0.f, 0.f, 0.f, 0.f);
            if (yy >= 0 && yy < Hh && xx >= 0 && xx < Wd)
                av = *(const float4*)(in + (size_t)((bimg * Hh + yy) * Wd + xx) * IC + ic);
            As[akg + 0][apix] = av.x;
            As[akg + 1][apix] = av.y;
            As[akg + 2][apix] = av.z;
            As[akg + 3][apix] = av.w;
        }
        // ---- load W tile ----
        {
            float4 wv = make_float4(0.f, 0.f, 0.f, 0.f);
            if (wvalid) wv = *(const float4*)(wrow + k0 + wkg);
            Wsm[wkg + 0][woc] = wv.x;
            Wsm[wkg + 1][woc] = wv.y;
            Wsm[wkg + 2][woc] = wv.z;
            Wsm[wkg + 3][woc] = wv.w;
        }
        __syncthreads();

#pragma unroll
        for (int k = 0; k < 16; k++) {
            float4 a = *(const float4*)&As[k][ty * 4];
            float4 b = *(const float4*)&Wsm[k][tx * 4];
            acc[0][0] += a.x * b.x; acc[0][1] += a.x * b.y; acc[0][2] += a.x * b.z; acc[0][3] += a.x * b.w;
            acc[1][0] += a.y * b.x; acc[1][1] += a.y * b.y; acc[1][2] += a.y * b.z; acc[1][3] += a.y * b.w;
            acc[2][0] += a.z * b.x; acc[2][1] += a.z * b.y; acc[2][2] += a.z * b.z; acc[2][3] += a.z * b.w;
            acc[3][0] += a.w * b.x; acc[3][1] += a.w * b.y; acc[3][2] += a.w * b.z; acc[3][3] += a.w * b.w;
        }
        __syncthreads();
    }

    const int ocb = ob + tx * 4;
    if (ocb < OC) {
        float4 bv = *(const float4*)(bias + ocb);
#pragma unroll
        for (int i = 0; i < 4; i++) {
            int p = pb + ty * 4 + i;
            float4 r;
            r.x = acc[i][0] + bv.x;
            r.y = acc[i][1] + bv.y;
            r.z = acc[i][2] + bv.z;
            r.w = acc[i][3] + bv.w;
            if (act) {
                r.x = r.x >= 0.f ? r.x : 0.2f * r.x;
                r.y = r.y >= 0.f ? r.y : 0.2f * r.y;
                r.z = r.z >= 0.f ? r.z : 0.2f * r.z;
                r.w = r.w >= 0.f ? r.w : 0.2f * r.w;
            }
            *(float4*)(out + (size_t)p * OC + ocb) = r;
        }
    }
}

// ---------------- windowed attention ---------------------------------------
// grid (NWIN, NHEAD), block 64 threads (one per window element).
// head h reads q/k from branch h/2 (channel offset (h&1)*32 / 64+(h&1)*32),
// v from g_v at h*32. Output (window, n, head*32+d) into g_pre.
__global__ void __launch_bounds__(64)
attn_kernel(const float* __restrict__ qk1, const float* __restrict__ qk3,
            const float* __restrict__ qk5, const float* __restrict__ vv,
            const float* __restrict__ rpb, float* __restrict__ outp) {
    const int wi   = blockIdx.x;
    const int head = blockIdx.y;
    const float* br = (head < 2) ? qk1 : ((head < 4) ? qk3 : qk5);
    const int qoff = (head & 1) * 32;

    __shared__ float4 Ks[64][8];
    __shared__ float4 Vs[64][8];

    const int n = threadIdx.x;
    const int b = wi >> 10, wh = (wi >> 5) & 31, wb = wi & 31;
    const int r = n >> 3, c = n & 7;
    const size_t p = ((size_t)(b * HH + wh * 8 + r) * WW + (wb * 8 + c));

    const float4* qp = (const float4*)(br + p * 128 + qoff);
    const float4* kp = (const float4*)(br + p * 128 + 64 + qoff);
    const float4* vp = (const float4*)(vv + p * 192 + head * 32);

    const float SC = 0.1767766952966369f; // 32^-0.5
    float4 q[8];
#pragma unroll
    for (int i = 0; i < 8; i++) {
        float4 qv = qp[i];
        qv.x *= SC; qv.y *= SC; qv.z *= SC; qv.w *= SC;
        q[i] = qv;
        Ks[n][i] = kp[i];
        Vs[n][i] = vp[i];
    }
    __syncthreads();

    float s[64];
    float mx = -1e30f;
#pragma unroll
    for (int m = 0; m < 64; m++) {
        float d = 0.f;
#pragma unroll
        for (int i = 0; i < 8; i++) {
            float4 kv = Ks[m][i];
            d += q[i].x * kv.x + q[i].y * kv.y + q[i].z * kv.z + q[i].w * kv.w;
        }
        int r2 = m >> 3, c2 = m & 7;
        d += rpb[((r - r2 + 7) * 15 + (c - c2 + 7)) * NHEAD + head];
        s[m] = d;
        mx = fmaxf(mx, d);
    }
    float sum = 0.f;
#pragma unroll
    for (int m = 0; m < 64; m++) {
        float e = __expf(s[m] - mx);
        s[m] = e;
        sum += e;
    }
    float4 acc[8];
#pragma unroll
    for (int i = 0; i < 8; i++) acc[i] = make_float4(0.f, 0.f, 0.f, 0.f);
#pragma unroll
    for (int m = 0; m < 64; m++) {
        float w = s[m];
#pragma unroll
        for (int i = 0; i < 8; i++) {
            float4 v4 = Vs[m][i];
            acc[i].x += w * v4.x; acc[i].y += w * v4.y;
            acc[i].z += w * v4.z; acc[i].w += w * v4.w;
        }
    }
    const float inv = 1.f / sum;
    float4* op = (float4*)(outp + ((size_t)wi * 64 + n) * 192 + head * 32);
#pragma unroll
    for (int i = 0; i < 8; i++) {
        float4 o = acc[i];
        o.x *= inv; o.y *= inv; o.z *= inv; o.w *= inv;
        op[i] = o;
    }
}

// ---------------- host launch ----------------------------------------------
extern "C" void kernel_launch(void* const* d_in, const int* in_sizes, int n_in,
                              void* d_out, int out_size) {
    (void)in_sizes; (void)n_in; (void)out_size;
    const float* x      = (const float*)d_in[0];
    const float* v_w    = (const float*)d_in[1];
    const float* v_b    = (const float*)d_in[2];
    const float* qk1_w  = (const float*)d_in[3];
    const float* qk1_b  = (const float*)d_in[4];
    const float* qk3_w1 = (const float*)d_in[5];
    const float* qk3_b1 = (const float*)d_in[6];
    const float* qk3_w2 = (const float*)d_in[7];
    const float* qk3_b2 = (const float*)d_in[8];
    const float* qk3_w3 = (const float*)d_in[9];
    const float* qk3_b3 = (const float*)d_in[10];
    const float* qk5_w1 = (const float*)d_in[11];
    const float* qk5_b1 = (const float*)d_in[12];
    const float* qk5_w2 = (const float*)d_in[13];
    const float* qk5_b2 = (const float*)d_in[14];
    const float* qk5_w3 = (const float*)d_in[15];
    const float* qk5_b3 = (const float*)d_in[16];
    const float* rpb    = (const float*)d_in[17];
    const float* proj_w = (const float*)d_in[18];
    const float* proj_b = (const float*)d_in[19];
    float* out = (float*)d_out;

    float *pv, *pqk1, *pt3a, *pt3b, *pqk3, *pt5a, *pt5b, *pqk5, *ppre;
    float *pw3a, *pw3c, *pw5a, *pw5c;
    cudaGetSymbolAddress((void**)&pv,   g_v);
    cudaGetSymbolAddress((void**)&pqk1, g_qk1);
    cudaGetSymbolAddress((void**)&pt3a, g_t3a);
    cudaGetSymbolAddress((void**)&pt3b, g_t3b);
    cudaGetSymbolAddress((void**)&pqk3, g_qk3);
    cudaGetSymbolAddress((void**)&pt5a, g_t5a);
    cudaGetSymbolAddress((void**)&pt5b, g_t5b);
    cudaGetSymbolAddress((void**)&pqk5, g_qk5);
    cudaGetSymbolAddress((void**)&ppre, g_pre);
    cudaGetSymbolAddress((void**)&pw3a, g_w3a);
    cudaGetSymbolAddress((void**)&pw3c, g_w3c);
    cudaGetSymbolAddress((void**)&pw5a, g_w5a);
    cudaGetSymbolAddress((void**)&pw5c, g_w5c);

    // repack spatial-conv weights
    repack_w<<<(32 * 192 * 9  + 255) / 256, 256>>>(qk3_w1, pw3a, 32, 192, 3, 3);
    repack_w<<<(128 * 32 * 9  + 255) / 256, 256>>>(qk3_w3, pw3c, 128, 32, 3, 3);
    repack_w<<<(16 * 192 * 25 + 255) / 256, 256>>>(qk5_w1, pw5a, 16, 192, 5, 5);
    repack_w<<<(128 * 16 * 25 + 255) / 256, 256>>>(qk5_w3, pw5c, 128, 16, 5, 5);

    const int PB = NPIX / 64;
    // v projection (1x1, 192->192)
    conv_gemm<<<dim3(PB, 3), 256>>>(x, v_w, v_b, pv, HH, WW, 192, 192, 1, 1, 0, 0);
    // branch 1: single 1x1, 192->128
    conv_gemm<<<dim3(PB, 2), 256>>>(x, qk1_w, qk1_b, pqk1, HH, WW, 192, 128, 1, 1, 0, 0);
    // branch 3: conv3 -> lrelu -> conv1 -> lrelu -> conv3
    conv_gemm<<<dim3(PB, 1), 256>>>(x, pw3a, qk3_b1, pt3a, HH, WW, 192, 32, 3, 3, 1, 1);
    conv_gemm<<<dim3(PB, 1), 256>>>(pt3a, qk3_w2, qk3_b2, pt3b, HH, WW, 32, 32, 1, 1, 0, 1);
    conv_gemm<<<dim3(PB, 2), 256>>>(pt3b, pw3c, qk3_b3, pqk3, HH, WW, 32, 128, 3, 3, 1, 0);
    // branch 5: conv5 -> lrelu -> conv1 -> lrelu -> conv5
    conv_gemm<<<dim3(PB, 1), 256>>>(x, pw5a, qk5_b1, pt5a, HH, WW, 192, 16, 5, 5, 2, 1);
    conv_gemm<<<dim3(PB, 1), 256>>>(pt5a, qk5_w2, qk5_b2, pt5b, HH, WW, 16, 16, 1, 1, 0, 1);
    conv_gemm<<<dim3(PB, 2), 256>>>(pt5b, pw5c, qk5_b3, pqk5, HH, WW, 16, 128, 5, 5, 2, 0);
    // windowed attention
    attn_kernel<<<dim3(NWIN, NHEAD), 64>>>(pqk1, pqk3, pqk5, pv, rpb, ppre);
    // output projection (1x1 GEMM over all window elements)
    conv_gemm<<<dim3(PB, 3), 256>>>(ppre, proj_w, proj_b, out, HH, WW, 192, 192, 1, 1, 0, 0);
}

// round 5
// speedup vs baseline: 2.4843x; 2.4843x over previous
#include <cuda_runtime.h>
#include <math.h>
#include <stdint.h>

// Problem constants (fixed by setup_inputs)
#define WSZ   8
#define NHEAD 6
#define HDIM  32
#define CDIM  192
#define BIMG  4
#define HH    256
#define WW    256
#define NPIX  (BIMG*HH*WW)        // 262144
#define NWIN  (BIMG*(HH/WSZ)*(WW/WSZ)) // 4096

// ---------------- scratch (device globals; no allocation allowed) ----------
__device__ __align__(16) float g_v  [NPIX*192];
__device__ __align__(16) float g_qk1[NPIX*128];
__device__ __align__(16) float g_t3a[NPIX*32];
__device__ __align__(16) float g_t3b[NPIX*32];
__device__ __align__(16) float g_qk3[NPIX*128];
__device__ __align__(16) float g_t5a[NPIX*16];
__device__ __align__(16) float g_t5b[NPIX*16];
__device__ __align__(16) float g_qk5[NPIX*128];
__device__ __align__(16) float g_pre[NPIX*192];
// repacked conv weights: (OC, K) with k = (kh*KW+kw)*IC + ic
__device__ __align__(16) float g_w3a[32*192*9];
__device__ __align__(16) float g_w3c[128*32*9];
__device__ __align__(16) float g_w5a[16*192*25];
__device__ __align__(16) float g_w5c[128*16*25];

// ---------------- weight repack: (OC,IC,KH,KW) -> (OC, tap*IC+ic) ---------
__global__ void repack_w(const float* __restrict__ src, float* __restrict__ dst,
                         int OC, int IC, int KH, int KW) {
    int Kt = IC * KH * KW;
    int i = blockIdx.x * 256 + threadIdx.x;
    if (i >= OC * Kt) return;
    int oc = i / Kt, k = i % Kt;
    int ic = k % IC;
    int tap = k / IC;
    int kh = tap / KW, kw = tap % KW;
    dst[i] = src[((size_t)(oc * IC + ic) * KH + kh) * KW + kw];
}

// ---------------- tf32 helpers ---------------------------------------------
__device__ __forceinline__ uint32_t f2tf32(float f) {
    uint32_t u;
    asm("cvt.rna.tf32.f32 %0, %1;" : "=r"(u) : "f"(f));
    return u;
}

__device__ __forceinline__ void mma_tf32(float* c, const uint32_t* a, const uint32_t* b) {
    asm volatile(
        "mma.sync.aligned.m16n8k8.row.col.f32.tf32.tf32.f32 "
        "{%0,%1,%2,%3},{%4,%5,%6,%7},{%8,%9},{%0,%1,%2,%3};"
        : "+f"(c[0]), "+f"(c[1]), "+f"(c[2]), "+f"(c[3])
        : "r"(a[0]), "r"(a[1]), "r"(a[2]), "r"(a[3]), "r"(b[0]), "r"(b[1]));
}

// ---------------- implicit-GEMM conv via tf32 tensor-core MMA --------------
// out[p, oc] = act( bias[oc] + sum_k A[p,k] * W[oc,k] ),  k = tap*IC + ic
// Tile: BM=128 pixels x BN oc x BK=16 k.  256 threads (8 warps).
// BN is chosen so OC % BN == 0 for every conv in this net (192/128/32/16).
template<int BN>
__global__ void __launch_bounds__(256)
conv_mma(const float* __restrict__ in, const float* __restrict__ wt,
         const float* __restrict__ bias, float* __restrict__ out,
         int Hh, int Wd, int IC, int OC, int KH, int KW, int pad, int act) {
    constexpr int BM = 128, BK = 16;
    constexpr int WN      = (BN == 64) ? 32 : BN;   // warp tile N
    constexpr int WARPS_N = BN / WN;                // 2 or 1
    constexpr int WARPS_M = 8 / WARPS_N;            // 4 or 8
    constexpr int WM      = BM / WARPS_M;           // 32 or 16
    constexpr int MT = WM / 16;                     // m16 tiles per warp
    constexpr int NT = WN / 8;                      // n8 tiles per warp

    __shared__ uint32_t As[BK][BM + 4];
    __shared__ uint32_t Ws[BK][BN + 4];

    const int Ktot = IC * KH * KW;
    const int tid  = threadIdx.x;
    const int lane = tid & 31;
    const int wid  = tid >> 5;
    const int g  = lane >> 2;      // group id 0..7
    const int tg = lane & 3;       // thread-in-group 0..3
    const int warp_m = wid % WARPS_M;
    const int warp_n = wid / WARPS_M;

    const int pb = blockIdx.x * BM;
    const int ob = blockIdx.y * BN;

    // ---- A loader mapping: 2 tasks of (pixel, 4 consecutive k) ----
    const int apix = tid >> 2;          // 0..63  (task1 adds +64)
    const int akq  = (tid & 3) * 4;     // k offset within BK
    int ry[2], rx[2], bb[2];
#pragma unroll
    for (int t = 0; t < 2; t++) {
        int pidx = pb + apix + t * 64;
        bb[t] = pidx / (Hh * Wd);
        ry[t] = (pidx / Wd) % Hh;
        rx[t] = pidx % Wd;
    }

    // ---- W loader mapping: tid < BN*4 loads one float4 ----
    const int woc = tid >> 2;
    const int wkq = (tid & 3) * 4;
    const bool wact = (tid < BN * 4);
    const float* wrow = wt + (size_t)(ob + woc) * Ktot;

    float acc[MT][NT][4];
#pragma unroll
    for (int mt = 0; mt < MT; mt++)
#pragma unroll
        for (int nt = 0; nt < NT; nt++)
#pragma unroll
            for (int i = 0; i < 4; i++) acc[mt][nt][i] = 0.f;

    for (int k0 = 0; k0 < Ktot; k0 += BK) {
        // ---- A tile (im2col on the fly; 4 consecutive ic share one tap) ----
        {
            int kk  = k0 + akq;
            int ic  = kk % IC;
            int tap = kk / IC;
            int kh = tap / KW, kw = tap % KW;
#pragma unroll
            for (int t = 0; t < 2; t++) {
                int yy = ry[t] + kh - pad, xx = rx[t] + kw - pad;
                float4 av = make_float4(0.f, 0.f, 0.f, 0.f);
                if (yy >= 0 && yy < Hh && xx >= 0 && xx < Wd)
                    av = *(const float4*)(in + (size_t)((bb[t] * Hh + yy) * Wd + xx) * IC + ic);
                int m = apix + t * 64;
                As[akq + 0][m] = f2tf32(av.x);
                As[akq + 1][m] = f2tf32(av.y);
                As[akq + 2][m] = f2tf32(av.z);
                As[akq + 3][m] = f2tf32(av.w);
            }
        }
        // ---- W tile ----
        if (wact) {
            float4 wv = *(const float4*)(wrow + k0 + wkq);
            Ws[wkq + 0][woc] = f2tf32(wv.x);
            Ws[wkq + 1][woc] = f2tf32(wv.y);
            Ws[wkq + 2][woc] = f2tf32(wv.z);
            Ws[wkq + 3][woc] = f2tf32(wv.w);
        }
        __syncthreads();

#pragma unroll
        for (int ks = 0; ks < 2; ks++) {
            const int kb = ks * 8;
            uint32_t af[MT][4];
            uint32_t bf[NT][2];
#pragma unroll
            for (int mt = 0; mt < MT; mt++) {
                int m0 = warp_m * WM + mt * 16;
                af[mt][0] = As[kb + tg    ][m0 + g];
                af[mt][1] = As[kb + tg    ][m0 + g + 8];
                af[mt][2] = As[kb + tg + 4][m0 + g];
                af[mt][3] = As[kb + tg + 4][m0 + g + 8];
            }
#pragma unroll
            for (int nt = 0; nt < NT; nt++) {
                int n0 = warp_n * WN + nt * 8;
                bf[nt][0] = Ws[kb + tg    ][n0 + g];
                bf[nt][1] = Ws[kb + tg + 4][n0 + g];
            }
#pragma unroll
            for (int mt = 0; mt < MT; mt++)
#pragma unroll
                for (int nt = 0; nt < NT; nt++)
                    mma_tf32(acc[mt][nt], af[mt], bf[nt]);
        }
        __syncthreads();
    }

    // ---- epilogue: bias + leaky-relu + store ----
#pragma unroll
    for (int nt = 0; nt < NT; nt++) {
        const int col = ob + warp_n * WN + nt * 8 + 2 * tg;
        const float2 b2 = *(const float2*)(bias + col);
#pragma unroll
        for (int mt = 0; mt < MT; mt++) {
            const int r0 = pb + warp_m * WM + mt * 16 + g;
#pragma unroll
            for (int h = 0; h < 2; h++) {
                int rr = r0 + h * 8;
                float2 v;
                v.x = acc[mt][nt][h * 2 + 0] + b2.x;
                v.y = acc[mt][nt][h * 2 + 1] + b2.y;
                if (act) {
                    v.x = v.x >= 0.f ? v.x : 0.2f * v.x;
                    v.y = v.y >= 0.f ? v.y : 0.2f * v.y;
                }
                *(float2*)(out + (size_t)rr * OC + col) = v;
            }
        }
    }
}

// ---------------- windowed attention ---------------------------------------
__global__ void __launch_bounds__(64)
attn_kernel(const float* __restrict__ qk1, const float* __restrict__ qk3,
            const float* __restrict__ qk5, const float* __restrict__ vv,
            const float* __restrict__ rpb, float* __restrict__ outp) {
    const int wi   = blockIdx.x;
    const int head = blockIdx.y;
    const float* br = (head < 2) ? qk1 : ((head < 4) ? qk3 : qk5);
    const int qoff = (head & 1) * 32;

    __shared__ float4 Ks[64][8];
    __shared__ float4 Vs[64][8];

    const int n = threadIdx.x;
    const int b = wi >> 10, wh = (wi >> 5) & 31, wb = wi & 31;
    const int r = n >> 3, c = n & 7;
    const size_t p = ((size_t)(b * HH + wh * 8 + r) * WW + (wb * 8 + c));

    const float4* qp = (const float4*)(br + p * 128 + qoff);
    const float4* kp = (const float4*)(br + p * 128 + 64 + qoff);
    const float4* vp = (const float4*)(vv + p * 192 + head * 32);

    const float SC = 0.1767766952966369f; // 32^-0.5
    float4 q[8];
#pragma unroll
    for (int i = 0; i < 8; i++) {
        float4 qv = qp[i];
        qv.x *= SC; qv.y *= SC; qv.z *= SC; qv.w *= SC;
        q[i] = qv;
        Ks[n][i] = kp[i];
        Vs[n][i] = vp[i];
    }
    __syncthreads();

    float s[64];
    float mx = -1e30f;
#pragma unroll
    for (int m = 0; m < 64; m++) {
        float d = 0.f;
#pragma unroll
        for (int i = 0; i < 8; i++) {
            float4 kv = Ks[m][i];
            d += q[i].x * kv.x + q[i].y * kv.y + q[i].z * kv.z + q[i].w * kv.w;
        }
        int r2 = m >> 3, c2 = m & 7;
        d += rpb[((r - r2 + 7) * 15 + (c - c2 + 7)) * NHEAD + head];
        s[m] = d;
        mx = fmaxf(mx, d);
    }
    float sum = 0.f;
#pragma unroll
    for (int m = 0; m < 64; m++) {
        float e = __expf(s[m] - mx);
        s[m] = e;
        sum += e;
    }
    float4 acc[8];
#pragma unroll
    for (int i = 0; i < 8; i++) acc[i] = make_float4(0.f, 0.f, 0.f, 0.f);
#pragma unroll
    for (int m = 0; m < 64; m++) {
        float w = s[m];
#pragma unroll
        for (int i = 0; i < 8; i++) {
            float4 v4 = Vs[m][i];
            acc[i].x += w * v4.x; acc[i].y += w * v4.y;
            acc[i].z += w * v4.z; acc[i].w += w * v4.w;
        }
    }
    const float inv = 1.f / sum;
    float4* op = (float4*)(outp + ((size_t)wi * 64 + n) * 192 + head * 32);
#pragma unroll
    for (int i = 0; i < 8; i++) {
        float4 o = acc[i];
        o.x *= inv; o.y *= inv; o.z *= inv; o.w *= inv;
        op[i] = o;
    }
}

// ---------------- host launch ----------------------------------------------
extern "C" void kernel_launch(void* const* d_in, const int* in_sizes, int n_in,
                              void* d_out, int out_size) {
    (void)in_sizes; (void)n_in; (void)out_size;
    const float* x      = (const float*)d_in[0];
    const float* v_w    = (const float*)d_in[1];
    const float* v_b    = (const float*)d_in[2];
    const float* qk1_w  = (const float*)d_in[3];
    const float* qk1_b  = (const float*)d_in[4];
    const float* qk3_w1 = (const float*)d_in[5];
    const float* qk3_b1 = (const float*)d_in[6];
    const float* qk3_w2 = (const float*)d_in[7];
    const float* qk3_b2 = (const float*)d_in[8];
    const float* qk3_w3 = (const float*)d_in[9];
    const float* qk3_b3 = (const float*)d_in[10];
    const float* qk5_w1 = (const float*)d_in[11];
    const float* qk5_b1 = (const float*)d_in[12];
    const float* qk5_w2 = (const float*)d_in[13];
    const float* qk5_b2 = (const float*)d_in[14];
    const float* qk5_w3 = (const float*)d_in[15];
    const float* qk5_b3 = (const float*)d_in[16];
    const float* rpb    = (const float*)d_in[17];
    const float* proj_w = (const float*)d_in[18];
    const float* proj_b = (const float*)d_in[19];
    float* out = (float*)d_out;

    float *pv, *pqk1, *pt3a, *pt3b, *pqk3, *pt5a, *pt5b, *pqk5, *ppre;
    float *pw3a, *pw3c, *pw5a, *pw5c;
    cudaGetSymbolAddress((void**)&pv,   g_v);
    cudaGetSymbolAddress((void**)&pqk1, g_qk1);
    cudaGetSymbolAddress((void**)&pt3a, g_t3a);
    cudaGetSymbolAddress((void**)&pt3b, g_t3b);
    cudaGetSymbolAddress((void**)&pqk3, g_qk3);
    cudaGetSymbolAddress((void**)&pt5a, g_t5a);
    cudaGetSymbolAddress((void**)&pt5b, g_t5b);
    cudaGetSymbolAddress((void**)&pqk5, g_qk5);
    cudaGetSymbolAddress((void**)&ppre, g_pre);
    cudaGetSymbolAddress((void**)&pw3a, g_w3a);
    cudaGetSymbolAddress((void**)&pw3c, g_w3c);
    cudaGetSymbolAddress((void**)&pw5a, g_w5a);
    cudaGetSymbolAddress((void**)&pw5c, g_w5c);

    // repack spatial-conv weights
    repack_w<<<(32 * 192 * 9  + 255) / 256, 256>>>(qk3_w1, pw3a, 32, 192, 3, 3);
    repack_w<<<(128 * 32 * 9  + 255) / 256, 256>>>(qk3_w3, pw3c, 128, 32, 3, 3);
    repack_w<<<(16 * 192 * 25 + 255) / 256, 256>>>(qk5_w1, pw5a, 16, 192, 5, 5);
    repack_w<<<(128 * 16 * 25 + 255) / 256, 256>>>(qk5_w3, pw5c, 128, 16, 5, 5);

    const int PB = NPIX / 128;
    // v projection (1x1, 192->192)
    conv_mma<64><<<dim3(PB, 3), 256>>>(x, v_w, v_b, pv, HH, WW, 192, 192, 1, 1, 0, 0);
    // branch 1: single 1x1, 192->128
    conv_mma<64><<<dim3(PB, 2), 256>>>(x, qk1_w, qk1_b, pqk1, HH, WW, 192, 128, 1, 1, 0, 0);
    // branch 3: conv3 -> lrelu -> conv1 -> lrelu -> conv3
    conv_mma<32><<<dim3(PB, 1), 256>>>(x, pw3a, qk3_b1, pt3a, HH, WW, 192, 32, 3, 3, 1, 1);
    conv_mma<32><<<dim3(PB, 1), 256>>>(pt3a, qk3_w2, qk3_b2, pt3b, HH, WW, 32, 32, 1, 1, 0, 1);
    conv_mma<64><<<dim3(PB, 2), 256>>>(pt3b, pw3c, qk3_b3, pqk3, HH, WW, 32, 128, 3, 3, 1, 0);
    // branch 5: conv5 -> lrelu -> conv1 -> lrelu -> conv5
    conv_mma<16><<<dim3(PB, 1), 256>>>(x, pw5a, qk5_b1, pt5a, HH, WW, 192, 16, 5, 5, 2, 1);
    conv_mma<16><<<dim3(PB, 1), 256>>>(pt5a, qk5_w2, qk5_b2, pt5b, HH, WW, 16, 16, 1, 1, 0, 1);
    conv_mma<64><<<dim3(PB, 2), 256>>>(pt5b, pw5c, qk5_b3, pqk5, HH, WW, 16, 128, 5, 5, 2, 0);
    // windowed attention
    attn_kernel<<<dim3(NWIN, NHEAD), 64>>>(pqk1, pqk3, pqk5, pv, rpb, ppre);
    // output projection (1x1 GEMM over all window elements)
    conv_mma<64><<<dim3(PB, 3), 256>>>(ppre, proj_w, proj_b, out, HH, WW, 192, 192, 1, 1, 0, 0);
}

// round 6
// speedup vs baseline: 3.5830x; 1.4422x over previous
#include <cuda_runtime.h>
#include <math.h>
#include <stdint.h>

// Problem constants (fixed by setup_inputs)
#define WSZ   8
#define NHEAD 6
#define HDIM  32
#define CDIM  192
#define BIMG  4
#define HH    256
#define WW    256
#define NPIX  (BIMG*HH*WW)        // 262144
#define NWIN  (BIMG*(HH/WSZ)*(WW/WSZ)) // 4096

// ---------------- scratch (device globals; no allocation allowed) ----------
__device__ __align__(16) float g_v  [NPIX*192];
__device__ __align__(16) float g_qk1[NPIX*128];
__device__ __align__(16) float g_t3a[NPIX*32];
__device__ __align__(16) float g_t3b[NPIX*32];
__device__ __align__(16) float g_qk3[NPIX*128];
__device__ __align__(16) float g_t5a[NPIX*16];
__device__ __align__(16) float g_t5b[NPIX*16];
__device__ __align__(16) float g_qk5[NPIX*128];
__device__ __align__(16) float g_pre[NPIX*192];
// repacked conv weights: (OC, K) with k = (kh*KW+kw)*IC + ic
__device__ __align__(16) float g_w3a[32*192*9];
__device__ __align__(16) float g_w3c[128*32*9];
__device__ __align__(16) float g_w5a[16*192*25];
__device__ __align__(16) float g_w5c[128*16*25];

// ---------------- weight repack: (OC,IC,KH,KW) -> (OC, tap*IC+ic) ---------
__global__ void repack_w(const float* __restrict__ src, float* __restrict__ dst,
                         int OC, int IC, int KH, int KW) {
    int Kt = IC * KH * KW;
    int i = blockIdx.x * 256 + threadIdx.x;
    if (i >= OC * Kt) return;
    int oc = i / Kt, k = i % Kt;
    int ic = k % IC;
    int tap = k / IC;
    int kh = tap / KW, kw = tap % KW;
    dst[i] = src[((size_t)(oc * IC + ic) * KH + kh) * KW + kw];
}

// ---------------- tf32 / cp.async helpers ----------------------------------
__device__ __forceinline__ uint32_t f2tf32(float f) {
    uint32_t u;
    asm("cvt.rna.tf32.f32 %0, %1;" : "=r"(u) : "f"(f));
    return u;
}

__device__ __forceinline__ void mma_tf32(float* c, const uint32_t* a, const uint32_t* b) {
    asm volatile(
        "mma.sync.aligned.m16n8k8.row.col.f32.tf32.tf32.f32 "
        "{%0,%1,%2,%3},{%4,%5,%6,%7},{%8,%9},{%0,%1,%2,%3};"
        : "+f"(c[0]), "+f"(c[1]), "+f"(c[2]), "+f"(c[3])
        : "r"(a[0]), "r"(a[1]), "r"(a[2]), "r"(a[3]), "r"(b[0]), "r"(b[1]));
}

__device__ __forceinline__ void cp_async16(uint32_t smem_dst, const void* gsrc, bool pred) {
    int bytes = pred ? 16 : 0;   // src-size 0 -> zero-fill destination
    asm volatile("cp.async.cg.shared.global [%0], [%1], 16, %2;\n"
                 :: "r"(smem_dst), "l"(gsrc), "r"(bytes));
}

// ---------------- implicit-GEMM conv via tf32 MMA, cp.async 2-stage --------
// out[p, oc] = act( bias[oc] + sum_k A[p,k] * W[oc,k] ),  k = tap*IC + ic
// BN == OC for every conv in this net (16/32/128/192) -> A read once.
template<int BN>
__global__ void __launch_bounds__(256)
conv_mma(const float* __restrict__ in, const float* __restrict__ wt,
         const float* __restrict__ bias, float* __restrict__ out,
         int Hh, int Wd, int IC, int OC, int KH, int KW, int pad, int act) {
    constexpr int BM = 128, BK = 32, STR = BK + 4;
    constexpr int WARPS_N = (BN >= 128) ? 4 : ((BN >= 64) ? 2 : 1);
    constexpr int WN = BN / WARPS_N;
    constexpr int NT = WN / 8;
    constexpr int WARPS_M = 8 / WARPS_N;
    constexpr int WM = BM / WARPS_M;
    constexpr int MT = WM / 16;
    constexpr int ASZ  = BM * STR;
    constexpr int WSZB = BN * STR;
    constexpr int WTASKS = BN * 8;        // float4 loads for W tile
    constexpr int WPER = (WTASKS + 255) / 256;

    extern __shared__ float smem[];
    float* Asm = smem;              // [2][BM][STR]
    float* Wsm = smem + 2 * ASZ;    // [2][BN][STR]

    const int Ktot = IC * KH * KW;
    const int tid  = threadIdx.x;
    const int lane = tid & 31;
    const int wid  = tid >> 5;
    const int g  = lane >> 2;
    const int tg = lane & 3;
    const int warp_m = wid % WARPS_M;
    const int warp_n = wid / WARPS_M;
    const int pb = blockIdx.x * BM;
    const int ob = blockIdx.y * BN;

    // A loader: thread -> fixed k-quad, 4 pixels (stride 32)
    const int a_pix0 = tid >> 3;          // 0..31
    const int a_kq   = (tid & 7) * 4;     // 0..28
    int ry[4], rx[4], bb[4];
#pragma unroll
    for (int j = 0; j < 4; j++) {
        int pidx = pb + a_pix0 + 32 * j;
        bb[j] = pidx / (Hh * Wd);
        ry[j] = (pidx / Wd) % Hh;
        rx[j] = pidx % Wd;
    }
    int a_ic  = a_kq % IC;
    int a_tap = a_kq / IC;

    const uint32_t a_base = (uint32_t)__cvta_generic_to_shared(Asm);
    const uint32_t w_base = (uint32_t)__cvta_generic_to_shared(Wsm);

    auto load_stage = [&](int k0, int stage) {
        // ---- A tile (im2col on the fly) ----
        {
            int kk = k0 + a_kq;
            bool kok = (kk < Ktot);
            int kh = a_tap / KW, kw = a_tap % KW;
            uint32_t dst0 = a_base + (uint32_t)(stage * ASZ) * 4u;
#pragma unroll
            for (int j = 0; j < 4; j++) {
                int yy = ry[j] + kh - pad, xx = rx[j] + kw - pad;
                bool p = kok && yy >= 0 && yy < Hh && xx >= 0 && xx < Wd;
                const float* src = p ? in + (size_t)((bb[j] * Hh + yy) * Wd + xx) * IC + a_ic
                                     : in;
                int pix = a_pix0 + 32 * j;
                cp_async16(dst0 + (uint32_t)(pix * STR + a_kq) * 4u, src, p);
            }
        }
        // ---- W tile ----
        {
            uint32_t dst0 = w_base + (uint32_t)(stage * WSZB) * 4u;
#pragma unroll
            for (int j = 0; j < WPER; j++) {
                int task = tid + 256 * j;
                if (task < WTASKS) {
                    int oc = task >> 3, kq = (task & 7) * 4;
                    int kk = k0 + kq;
                    bool p = (kk < Ktot);
                    const float* src = wt + (size_t)(ob + oc) * Ktot + (p ? kk : 0);
                    cp_async16(dst0 + (uint32_t)(oc * STR + kq) * 4u, src, p);
                }
            }
        }
    };
    auto advance = [&]() {
        a_ic += BK;
        while (a_ic >= IC) { a_ic -= IC; a_tap++; }
    };

    float acc[MT][NT][4];
#pragma unroll
    for (int mt = 0; mt < MT; mt++)
#pragma unroll
        for (int nt = 0; nt < NT; nt++)
#pragma unroll
            for (int i = 0; i < 4; i++) acc[mt][nt][i] = 0.f;

    const int iters = (Ktot + BK - 1) / BK;
    load_stage(0, 0); advance();
    asm volatile("cp.async.commit_group;\n" ::);

    for (int i = 0; i < iters; i++) {
        if (i + 1 < iters) {
            load_stage((i + 1) * BK, (i + 1) & 1); advance();
            asm volatile("cp.async.commit_group;\n" ::);
            asm volatile("cp.async.wait_group 1;\n" ::);
        } else {
            asm volatile("cp.async.wait_group 0;\n" ::);
        }
        __syncthreads();

        const float* Ac = Asm + (i & 1) * ASZ;
        const float* Wc = Wsm + (i & 1) * WSZB;
#pragma unroll
        for (int ks = 0; ks < 4; ks++) {
            const int kb = ks * 8;
            uint32_t af[MT][4], bf[NT][2];
#pragma unroll
            for (int mt = 0; mt < MT; mt++) {
                const float* a = Ac + (warp_m * WM + mt * 16 + g) * STR + kb + tg;
                af[mt][0] = f2tf32(a[0]);
                af[mt][1] = f2tf32(a[8 * STR]);
                af[mt][2] = f2tf32(a[4]);
                af[mt][3] = f2tf32(a[8 * STR + 4]);
            }
#pragma unroll
            for (int nt = 0; nt < NT; nt++) {
                const float* w = Wc + (warp_n * WN + nt * 8 + g) * STR + kb + tg;
                bf[nt][0] = f2tf32(w[0]);
                bf[nt][1] = f2tf32(w[4]);
            }
#pragma unroll
            for (int mt = 0; mt < MT; mt++)
#pragma unroll
                for (int nt = 0; nt < NT; nt++)
                    mma_tf32(acc[mt][nt], af[mt], bf[nt]);
        }
        __syncthreads();
    }

    // ---- epilogue: bias + leaky-relu + store ----
#pragma unroll
    for (int nt = 0; nt < NT; nt++) {
        const int col = ob + warp_n * WN + nt * 8 + 2 * tg;
        const float2 b2 = *(const float2*)(bias + col);
#pragma unroll
        for (int mt = 0; mt < MT; mt++) {
            const int r0 = pb + warp_m * WM + mt * 16 + g;
#pragma unroll
            for (int h = 0; h < 2; h++) {
                int rr = r0 + h * 8;
                float2 v;
                v.x = acc[mt][nt][h * 2 + 0] + b2.x;
                v.y = acc[mt][nt][h * 2 + 1] + b2.y;
                if (act) {
                    v.x = v.x >= 0.f ? v.x : 0.2f * v.x;
                    v.y = v.y >= 0.f ? v.y : 0.2f * v.y;
                }
                *(float2*)(out + (size_t)rr * OC + col) = v;
            }
        }
    }
}

// ---------------- windowed attention ---------------------------------------
__global__ void __launch_bounds__(64)
attn_kernel(const float* __restrict__ qk1, const float* __restrict__ qk3,
            const float* __restrict__ qk5, const float* __restrict__ vv,
            const float* __restrict__ rpb, float* __restrict__ outp) {
    const int wi   = blockIdx.x;
    const int head = blockIdx.y;
    const float* br = (head < 2) ? qk1 : ((head < 4) ? qk3 : qk5);
    const int qoff = (head & 1) * 32;

    __shared__ float4 Ks[64][8];
    __shared__ float4 Vs[64][8];

    const int n = threadIdx.x;
    const int b = wi >> 10, wh = (wi >> 5) & 31, wb = wi & 31;
    const int r = n >> 3, c = n & 7;
    const size_t p = ((size_t)(b * HH + wh * 8 + r) * WW + (wb * 8 + c));

    const float4* qp = (const float4*)(br + p * 128 + qoff);
    const float4* kp = (const float4*)(br + p * 128 + 64 + qoff);
    const float4* vp = (const float4*)(vv + p * 192 + head * 32);

    const float SC = 0.1767766952966369f; // 32^-0.5
    float4 q[8];
#pragma unroll
    for (int i = 0; i < 8; i++) {
        float4 qv = qp[i];
        qv.x *= SC; qv.y *= SC; qv.z *= SC; qv.w *= SC;
        q[i] = qv;
        Ks[n][i] = kp[i];
        Vs[n][i] = vp[i];
    }
    __syncthreads();

    float s[64];
    float mx = -1e30f;
#pragma unroll
    for (int m = 0; m < 64; m++) {
        float d = 0.f;
#pragma unroll
        for (int i = 0; i < 8; i++) {
            float4 kv = Ks[m][i];
            d += q[i].x * kv.x + q[i].y * kv.y + q[i].z * kv.z + q[i].w * kv.w;
        }
        int r2 = m >> 3, c2 = m & 7;
        d += rpb[((r - r2 + 7) * 15 + (c - c2 + 7)) * NHEAD + head];
        s[m] = d;
        mx = fmaxf(mx, d);
    }
    float sum = 0.f;
#pragma unroll
    for (int m = 0; m < 64; m++) {
        float e = __expf(s[m] - mx);
        s[m] = e;
        sum += e;
    }
    float4 acc[8];
#pragma unroll
    for (int i = 0; i < 8; i++) acc[i] = make_float4(0.f, 0.f, 0.f, 0.f);
#pragma unroll
    for (int m = 0; m < 64; m++) {
        float w = s[m];
#pragma unroll
        for (int i = 0; i < 8; i++) {
            float4 v4 = Vs[m][i];
            acc[i].x += w * v4.x; acc[i].y += w * v4.y;
            acc[i].z += w * v4.z; acc[i].w += w * v4.w;
        }
    }
    const float inv = 1.f / sum;
    float4* op = (float4*)(outp + ((size_t)wi * 64 + n) * 192 + head * 32);
#pragma unroll
    for (int i = 0; i < 8; i++) {
        float4 o = acc[i];
        o.x *= inv; o.y *= inv; o.z *= inv; o.w *= inv;
        op[i] = o;
    }
}

// ---------------- host launch ----------------------------------------------
static inline constexpr int conv_smem(int bn) { return 288 * (128 + bn); } // 2*(128+BN)*36*4

extern "C" void kernel_launch(void* const* d_in, const int* in_sizes, int n_in,
                              void* d_out, int out_size) {
    (void)in_sizes; (void)n_in; (void)out_size;
    const float* x      = (const float*)d_in[0];
    const float* v_w    = (const float*)d_in[1];
    const float* v_b    = (const float*)d_in[2];
    const float* qk1_w  = (const float*)d_in[3];
    const float* qk1_b  = (const float*)d_in[4];
    const float* qk3_w1 = (const float*)d_in[5];
    const float* qk3_b1 = (const float*)d_in[6];
    const float* qk3_w2 = (const float*)d_in[7];
    const float* qk3_b2 = (const float*)d_in[8];
    const float* qk3_w3 = (const float*)d_in[9];
    const float* qk3_b3 = (const float*)d_in[10];
    const float* qk5_w1 = (const float*)d_in[11];
    const float* qk5_b1 = (const float*)d_in[12];
    const float* qk5_w2 = (const float*)d_in[13];
    const float* qk5_b2 = (const float*)d_in[14];
    const float* qk5_w3 = (const float*)d_in[15];
    const float* qk5_b3 = (const float*)d_in[16];
    const float* rpb    = (const float*)d_in[17];
    const float* proj_w = (const float*)d_in[18];
    const float* proj_b = (const float*)d_in[19];
    float* out = (float*)d_out;

    float *pv, *pqk1, *pt3a, *pt3b, *pqk3, *pt5a, *pt5b, *pqk5, *ppre;
    float *pw3a, *pw3c, *pw5a, *pw5c;
    cudaGetSymbolAddress((void**)&pv,   g_v);
    cudaGetSymbolAddress((void**)&pqk1, g_qk1);
    cudaGetSymbolAddress((void**)&pt3a, g_t3a);
    cudaGetSymbolAddress((void**)&pt3b, g_t3b);
    cudaGetSymbolAddress((void**)&pqk3, g_qk3);
    cudaGetSymbolAddress((void**)&pt5a, g_t5a);
    cudaGetSymbolAddress((void**)&pt5b, g_t5b);
    cudaGetSymbolAddress((void**)&pqk5, g_qk5);
    cudaGetSymbolAddress((void**)&ppre, g_pre);
    cudaGetSymbolAddress((void**)&pw3a, g_w3a);
    cudaGetSymbolAddress((void**)&pw3c, g_w3c);
    cudaGetSymbolAddress((void**)&pw5a, g_w5a);
    cudaGetSymbolAddress((void**)&pw5c, g_w5c);

    // opt-in dynamic smem (one-time state; harmless to repeat)
    cudaFuncSetAttribute(conv_mma<192>, cudaFuncAttributeMaxDynamicSharedMemorySize, conv_smem(192));
    cudaFuncSetAttribute(conv_mma<128>, cudaFuncAttributeMaxDynamicSharedMemorySize, conv_smem(128));
    cudaFuncSetAttribute(conv_mma<32>,  cudaFuncAttributeMaxDynamicSharedMemorySize, conv_smem(32));
    cudaFuncSetAttribute(conv_mma<16>,  cudaFuncAttributeMaxDynamicSharedMemorySize, conv_smem(16));

    // repack spatial-conv weights
    repack_w<<<(32 * 192 * 9  + 255) / 256, 256>>>(qk3_w1, pw3a, 32, 192, 3, 3);
    repack_w<<<(128 * 32 * 9  + 255) / 256, 256>>>(qk3_w3, pw3c, 128, 32, 3, 3);
    repack_w<<<(16 * 192 * 25 + 255) / 256, 256>>>(qk5_w1, pw5a, 16, 192, 5, 5);
    repack_w<<<(128 * 16 * 25 + 255) / 256, 256>>>(qk5_w3, pw5c, 128, 16, 5, 5);

    const int PB = NPIX / 128;
    // v projection (1x1, 192->192)
    conv_mma<192><<<PB, 256, conv_smem(192)>>>(x, v_w, v_b, pv, HH, WW, 192, 192, 1, 1, 0, 0);
    // branch 1: single 1x1, 192->128
    conv_mma<128><<<PB, 256, conv_smem(128)>>>(x, qk1_w, qk1_b, pqk1, HH, WW, 192, 128, 1, 1, 0, 0);
    // branch 3: conv3 -> lrelu -> conv1 -> lrelu -> conv3
    conv_mma<32><<<PB, 256, conv_smem(32)>>>(x, pw3a, qk3_b1, pt3a, HH, WW, 192, 32, 3, 3, 1, 1);
    conv_mma<32><<<PB, 256, conv_smem(32)>>>(pt3a, qk3_w2, qk3_b2, pt3b, HH, WW, 32, 32, 1, 1, 0, 1);
    conv_mma<128><<<PB, 256, conv_smem(128)>>>(pt3b, pw3c, qk3_b3, pqk3, HH, WW, 32, 128, 3, 3, 1, 0);
    // branch 5: conv5 -> lrelu -> conv1 -> lrelu -> conv5
    conv_mma<16><<<PB, 256, conv_smem(16)>>>(x, pw5a, qk5_b1, pt5a, HH, WW, 192, 16, 5, 5, 2, 1);
    conv_mma<16><<<PB, 256, conv_smem(16)>>>(pt5a, qk5_w2, qk5_b2, pt5b, HH, WW, 16, 16, 1, 1, 0, 1);
    conv_mma<128><<<PB, 256, conv_smem(128)>>>(pt5b, pw5c, qk5_b3, pqk5, HH, WW, 16, 128, 5, 5, 2, 0);
    // windowed attention
    attn_kernel<<<dim3(NWIN, NHEAD), 64>>>(pqk1, pqk3, pqk5, pv, rpb, ppre);
    // output projection (1x1 GEMM over all window elements)
    conv_mma<192><<<PB, 256, conv_smem(192)>>>(ppre, proj_w, proj_b, out, HH, WW, 192, 192, 1, 1, 0, 0);
}